// round 4
// baseline (speedup 1.0000x reference)
#include <cuda_runtime.h>
#include <cstdint>

#define NV 4096
#define ALPHA 0.2f

// ---------------- device scratch ----------------
__device__ float g_Wh[NV * 64];
__device__ float g_e1[NV], g_e2[NV];
__device__ float g_E1[NV], g_E2[NV];
__device__ float g_A[NV], g_B[NV], g_thE[NV], g_dinv[NV];
__device__ float g_part[8][NV * 64];

// ---------------- K1: Wh = H@W + e1/e2 (+ fused E1/E2 exps) ----------------
__global__ __launch_bounds__(256) void k1_wh(const float* __restrict__ H,
                                             const float* __restrict__ W,
                                             const float* __restrict__ a) {
    __shared__ float Hs[64][68];
    __shared__ float Ws[64][64];
    int tid = threadIdx.x;
    int tr = tid >> 4;   // row group of 4
    int tc = tid & 15;   // col group of 4
    int row0 = blockIdx.x * 64;

    unsigned long long acc[8];
#pragma unroll
    for (int q = 0; q < 8; q++) acc[q] = 0ull;

    for (int kk = 0; kk < 256; kk += 64) {
#pragma unroll
        for (int t = 0; t < 4; t++) {
            int u = tid + t * 256;
            int r = u >> 4, c4 = u & 15;
            *(float4*)&Hs[r][c4 * 4] = *(const float4*)&H[(size_t)(row0 + r) * 256 + kk + c4 * 4];
            *(float4*)&Ws[r][c4 * 4] = *(const float4*)&W[(size_t)(kk + r) * 64 + c4 * 4];
        }
        __syncthreads();
#pragma unroll 8
        for (int k = 0; k < 64; k++) {
            float4 w4 = *(const float4*)&Ws[k][tc * 4];
            unsigned long long w01, w23;
            asm("mov.b64 %0, {%1, %2};" : "=l"(w01) : "f"(w4.x), "f"(w4.y));
            asm("mov.b64 %0, {%1, %2};" : "=l"(w23) : "f"(w4.z), "f"(w4.w));
#pragma unroll
            for (int q = 0; q < 4; q++) {
                float h = Hs[tr * 4 + q][k];
                unsigned long long hp;
                asm("mov.b64 %0, {%1, %1};" : "=l"(hp) : "f"(h));
                asm("fma.rn.f32x2 %0, %1, %2, %0;" : "+l"(acc[q * 2 + 0]) : "l"(hp), "l"(w01));
                asm("fma.rn.f32x2 %0, %1, %2, %0;" : "+l"(acc[q * 2 + 1]) : "l"(hp), "l"(w23));
            }
        }
        __syncthreads();
    }

    float v[4][4];
#pragma unroll
    for (int q = 0; q < 4; q++) {
        v[q][0] = __uint_as_float((uint32_t)acc[q * 2 + 0]);
        v[q][1] = __uint_as_float((uint32_t)(acc[q * 2 + 0] >> 32));
        v[q][2] = __uint_as_float((uint32_t)acc[q * 2 + 1]);
        v[q][3] = __uint_as_float((uint32_t)(acc[q * 2 + 1] >> 32));
    }
    float a1c[4], a2c[4];
#pragma unroll
    for (int c = 0; c < 4; c++) {
        a1c[c] = __ldg(&a[tc * 4 + c]);
        a2c[c] = __ldg(&a[64 + tc * 4 + c]);
    }
#pragma unroll
    for (int q = 0; q < 4; q++) {
        int i = row0 + tr * 4 + q;
        *(float4*)&g_Wh[(size_t)i * 64 + tc * 4] = make_float4(v[q][0], v[q][1], v[q][2], v[q][3]);
        float p1 = v[q][0] * a1c[0] + v[q][1] * a1c[1] + v[q][2] * a1c[2] + v[q][3] * a1c[3];
        float p2 = v[q][0] * a2c[0] + v[q][1] * a2c[1] + v[q][2] * a2c[2] + v[q][3] * a2c[3];
#pragma unroll
        for (int off = 1; off < 16; off <<= 1) {
            p1 += __shfl_xor_sync(0xffffffffu, p1, off);
            p2 += __shfl_xor_sync(0xffffffffu, p2, off);
        }
        if (tc == 0) {
            g_e1[i] = p1;
            g_e2[i] = p2;
            g_E1[i] = __expf(p2);
            g_E2[i] = __expf(ALPHA * p2);
        }
    }
}

// ---------------- K2: per-row m, A, B, thE, 1/denominator (smem-staged) ------
__global__ __launch_bounds__(256) void k2_denom() {
    __shared__ float sE1[NV];
    __shared__ float sE2[NV];
    __shared__ float red[8];
    int tid = threadIdx.x;
#pragma unroll
    for (int t = 0; t < 4; t++) {
        ((float4*)sE1)[tid + t * 256] = ((const float4*)g_E1)[tid + t * 256];
        ((float4*)sE2)[tid + t * 256] = ((const float4*)g_E2)[tid + t * 256];
    }
    float mx = -1e30f;
#pragma unroll
    for (int t = 0; t < 4; t++) {
        float4 v = ((const float4*)g_e2)[tid + t * 256];
        mx = fmaxf(fmaxf(mx, v.x), fmaxf(fmaxf(v.y, v.z), v.w));
    }
#pragma unroll
    for (int o = 16; o > 0; o >>= 1) mx = fmaxf(mx, __shfl_xor_sync(0xffffffffu, mx, o));
    if ((tid & 31) == 0) red[tid >> 5] = mx;
    __syncthreads();
    float e2max = red[0];
#pragma unroll
    for (int w = 1; w < 8; w++) e2max = fmaxf(e2max, red[w]);

    int il = tid >> 4;
    int sub = tid & 15;
    int i = blockIdx.x * 16 + il;
    float e1v = g_e1[i];
    float s = e1v + e2max;
    float m = s > 0.f ? s : ALPHA * s;
    float A = __expf(e1v - m);
    float B = __expf(ALPHA * e1v - m);
    float thE = __expf(-e1v);

    float d = 0.f;
#pragma unroll 4
    for (int t = 0; t < 64; t++) {
        int j = sub * 4 + t * 64;
        float4 E1v = *(const float4*)&sE1[j];
        float4 E2v = *(const float4*)&sE2[j];
        d += (E1v.x > thE) ? A * E1v.x : B * E2v.x;
        d += (E1v.y > thE) ? A * E1v.y : B * E2v.y;
        d += (E1v.z > thE) ? A * E1v.z : B * E2v.z;
        d += (E1v.w > thE) ? A * E1v.w : B * E2v.w;
    }
#pragma unroll
    for (int o = 8; o > 0; o >>= 1) d += __shfl_xor_sync(0xffffffffu, d, o);
    if (sub == 0) {
        g_A[i] = A; g_B[i] = B; g_thE[i] = thE;
        g_dinv[i] = 1.f / d;
    }
}

// ---------------- K3: masked weighted GEMM ----------------
// Grid: 64 row-blocks (64 i) x 8 j-segments (512 j) = 512 CTAs, 128 threads.
// smem: ws[64j][64i] @0 (16KB), whdup[64j][64c] u64 pairs @16KB (32KB),
//       sE1[512] @48KB, sE2[512] @50KB -> 52KB; 4 CTAs/SM, 16 warps/SM.
// Inner loop per j: 4 LDS.128 + 16 FFMA2 (no packing movs).
#define K3_SMEM 53248
__global__ __launch_bounds__(128, 4) void k3_main(const int* __restrict__ adj) {
    extern __shared__ float sm[];
    float* ws = sm;                                          // [64][64]
    unsigned long long* whdup = (unsigned long long*)(sm + 4096);  // [64][64]
    float* sE1 = sm + 12288;                                 // [512]
    float* sE2 = sm + 12800;                                 // [512]

    int tid = threadIdx.x;
    int br = blockIdx.x >> 3;          // 0..63
    int jseg = blockIdx.x & 7;         // 0..7
    int jbase = jseg << 9;             // *512

    // stage E1/E2 for this segment (128 thr * 4 = 512)
    ((float4*)sE1)[tid] = ((const float4*)(g_E1 + jbase))[tid];
    ((float4*)sE2)[tid] = ((const float4*)(g_E2 + jbase))[tid];

    // build role: i-row brow, j-half jh (32 j)
    int brow = tid & 63;
    int jh = (tid >> 6) * 32;
    int gi = br * 64 + brow;
    float Ai = __ldg(&g_A[gi]), Bi = __ldg(&g_B[gi]), th = __ldg(&g_thE[gi]);
    const int4* adjp = (const int4*)(adj + (size_t)gi * NV + jbase + jh);

    // compute role: rows tr*8..+7, cols tc*4..+3
    int tr = tid >> 4;
    int tc = tid & 15;

    unsigned long long acc[16];
#pragma unroll
    for (int q = 0; q < 16; q++) acc[q] = 0ull;

    int4 pref[8];
#pragma unroll
    for (int q = 0; q < 8; q++) pref[q] = __ldg(adjp + q);

    for (int ch = 0; ch < 8; ++ch) {
        __syncthreads();   // prev chunk consumed (covers E staging on ch=0)

        // Wh chunk -> duplicated pairs whdup[j][c] = {v,v}
#pragma unroll
        for (int t = 0; t < 8; t++) {
            int u = tid + t * 128;
            int r = u >> 4, c4 = u & 15;
            float4 v = *(const float4*)&g_Wh[(size_t)(jbase + ch * 64 + r) * 64 + c4 * 4];
            unsigned long long d0, d1, d2, d3;
            asm("mov.b64 %0, {%1, %1};" : "=l"(d0) : "f"(v.x));
            asm("mov.b64 %0, {%1, %1};" : "=l"(d1) : "f"(v.y));
            asm("mov.b64 %0, {%1, %1};" : "=l"(d2) : "f"(v.z));
            asm("mov.b64 %0, {%1, %1};" : "=l"(d3) : "f"(v.w));
            unsigned long long* dst = &whdup[r * 64 + c4 * 4];
            *(ulonglong2*)(dst)     = make_ulonglong2(d0, d1);
            *(ulonglong2*)(dst + 2) = make_ulonglong2(d2, d3);
        }
        // build masked-weight tile ws[j][i] from pref
#pragma unroll
        for (int q = 0; q < 8; q++) {
            int4 av = pref[q];
            int jl = ch * 64 + jh + q * 4;
            float4 e1 = *(const float4*)&sE1[jl];
            float4 e2 = *(const float4*)&sE2[jl];
            float w0 = (av.x > 0) ? ((e1.x > th) ? Ai * e1.x : Bi * e2.x) : 0.f;
            float w1 = (av.y > 0) ? ((e1.y > th) ? Ai * e1.y : Bi * e2.y) : 0.f;
            float w2 = (av.z > 0) ? ((e1.z > th) ? Ai * e1.z : Bi * e2.z) : 0.f;
            float w3 = (av.w > 0) ? ((e1.w > th) ? Ai * e1.w : Bi * e2.w) : 0.f;
            int jr = (jh + q * 4) * 64 + brow;
            ws[jr]       = w0;
            ws[jr + 64]  = w1;
            ws[jr + 128] = w2;
            ws[jr + 192] = w3;
        }
        // prefetch next chunk's adj (after pref consumed)
        if (ch < 7) {
#pragma unroll
            for (int q = 0; q < 8; q++) pref[q] = __ldg(adjp + (ch + 1) * 16 + q);
        }
        __syncthreads();

        // compute
#pragma unroll 8
        for (int jj = 0; jj < 64; jj++) {
            ulonglong2 wA = *(const ulonglong2*)&ws[jj * 64 + tr * 8];
            ulonglong2 wB = *(const ulonglong2*)&ws[jj * 64 + tr * 8 + 4];
            ulonglong2 dd01 = *(const ulonglong2*)&whdup[jj * 64 + tc * 4];
            ulonglong2 dd23 = *(const ulonglong2*)&whdup[jj * 64 + tc * 4 + 2];
            asm("fma.rn.f32x2 %0, %1, %2, %0;" : "+l"(acc[0])  : "l"(wA.x), "l"(dd01.x));
            asm("fma.rn.f32x2 %0, %1, %2, %0;" : "+l"(acc[1])  : "l"(wA.x), "l"(dd01.y));
            asm("fma.rn.f32x2 %0, %1, %2, %0;" : "+l"(acc[2])  : "l"(wA.x), "l"(dd23.x));
            asm("fma.rn.f32x2 %0, %1, %2, %0;" : "+l"(acc[3])  : "l"(wA.x), "l"(dd23.y));
            asm("fma.rn.f32x2 %0, %1, %2, %0;" : "+l"(acc[4])  : "l"(wA.y), "l"(dd01.x));
            asm("fma.rn.f32x2 %0, %1, %2, %0;" : "+l"(acc[5])  : "l"(wA.y), "l"(dd01.y));
            asm("fma.rn.f32x2 %0, %1, %2, %0;" : "+l"(acc[6])  : "l"(wA.y), "l"(dd23.x));
            asm("fma.rn.f32x2 %0, %1, %2, %0;" : "+l"(acc[7])  : "l"(wA.y), "l"(dd23.y));
            asm("fma.rn.f32x2 %0, %1, %2, %0;" : "+l"(acc[8])  : "l"(wB.x), "l"(dd01.x));
            asm("fma.rn.f32x2 %0, %1, %2, %0;" : "+l"(acc[9])  : "l"(wB.x), "l"(dd01.y));
            asm("fma.rn.f32x2 %0, %1, %2, %0;" : "+l"(acc[10]) : "l"(wB.x), "l"(dd23.x));
            asm("fma.rn.f32x2 %0, %1, %2, %0;" : "+l"(acc[11]) : "l"(wB.x), "l"(dd23.y));
            asm("fma.rn.f32x2 %0, %1, %2, %0;" : "+l"(acc[12]) : "l"(wB.y), "l"(dd01.x));
            asm("fma.rn.f32x2 %0, %1, %2, %0;" : "+l"(acc[13]) : "l"(wB.y), "l"(dd01.y));
            asm("fma.rn.f32x2 %0, %1, %2, %0;" : "+l"(acc[14]) : "l"(wB.y), "l"(dd23.x));
            asm("fma.rn.f32x2 %0, %1, %2, %0;" : "+l"(acc[15]) : "l"(wB.y), "l"(dd23.y));
        }
    }

    // write partials: acc[ip*4+c] lo -> row tr*8+2ip, hi -> +1
    float* base = &g_part[jseg][(size_t)(br * 64 + tr * 8) * 64 + tc * 4];
#pragma unroll
    for (int ip = 0; ip < 4; ip++) {
        float4 lo, hi;
        lo.x = __uint_as_float((uint32_t)acc[ip * 4 + 0]);
        lo.y = __uint_as_float((uint32_t)acc[ip * 4 + 1]);
        lo.z = __uint_as_float((uint32_t)acc[ip * 4 + 2]);
        lo.w = __uint_as_float((uint32_t)acc[ip * 4 + 3]);
        hi.x = __uint_as_float((uint32_t)(acc[ip * 4 + 0] >> 32));
        hi.y = __uint_as_float((uint32_t)(acc[ip * 4 + 1] >> 32));
        hi.z = __uint_as_float((uint32_t)(acc[ip * 4 + 2] >> 32));
        hi.w = __uint_as_float((uint32_t)(acc[ip * 4 + 3] >> 32));
        *(float4*)(base + (ip * 2) * 64)     = lo;
        *(float4*)(base + (ip * 2 + 1) * 64) = hi;
    }
}

// ---------------- K4: combine 8 partials, scale, ELU (vectorized) -----------
__global__ __launch_bounds__(256) void k4_out(float* __restrict__ out) {
    int v4 = blockIdx.x * 256 + threadIdx.x;     // float4 index, 0..65535
    float4 s = ((const float4*)g_part[0])[v4];
#pragma unroll
    for (int p = 1; p < 8; p++) {
        float4 t = ((const float4*)g_part[p])[v4];
        s.x += t.x; s.y += t.y; s.z += t.z; s.w += t.w;
    }
    int i = v4 >> 4;       // row = (v4*4)/64
    float di = g_dinv[i];
    s.x *= di; s.y *= di; s.z *= di; s.w *= di;
    s.x = s.x > 0.f ? s.x : (__expf(s.x) - 1.f);
    s.y = s.y > 0.f ? s.y : (__expf(s.y) - 1.f);
    s.z = s.z > 0.f ? s.z : (__expf(s.z) - 1.f);
    s.w = s.w > 0.f ? s.w : (__expf(s.w) - 1.f);
    ((float4*)out)[v4] = s;
}

// ---------------- launch ----------------
extern "C" void kernel_launch(void* const* d_in, const int* in_sizes, int n_in,
                              void* d_out, int out_size) {
    const float* H = (const float*)d_in[0];
    const int* adj = (const int*)d_in[1];
    const float* W = (const float*)d_in[2];
    const float* a = (const float*)d_in[3];
    float* out = (float*)d_out;

    cudaFuncSetAttribute(k3_main, cudaFuncAttributeMaxDynamicSharedMemorySize, K3_SMEM);

    k1_wh<<<64, 256>>>(H, W, a);
    k2_denom<<<256, 256>>>();
    k3_main<<<512, 128, K3_SMEM>>>(adj);
    k4_out<<<256, 256>>>(out);
}

// round 5
// speedup vs baseline: 1.4938x; 1.4938x over previous
#include <cuda_runtime.h>
#include <cstdint>

#define NV 4096
#define ALPHA 0.2f

// ---------------- device scratch ----------------
__device__ float g_Wh[NV * 64];
__device__ float g_e1[NV], g_e2[NV];
__device__ float g_E1[NV], g_E2[NV];
__device__ float g_A[NV], g_B[NV], g_thE[NV], g_dinv[NV];
__device__ float g_part[8][NV * 64];

// ---------------- K1: Wh = H@W + e1/e2 (+ fused E1/E2 exps) ----------------
__global__ __launch_bounds__(256) void k1_wh(const float* __restrict__ H,
                                             const float* __restrict__ W,
                                             const float* __restrict__ a) {
    __shared__ float Hs[64][68];
    __shared__ float Ws[64][64];
    int tid = threadIdx.x;
    int tr = tid >> 4;
    int tc = tid & 15;
    int row0 = blockIdx.x * 64;

    unsigned long long acc[8];
#pragma unroll
    for (int q = 0; q < 8; q++) acc[q] = 0ull;

    for (int kk = 0; kk < 256; kk += 64) {
#pragma unroll
        for (int t = 0; t < 4; t++) {
            int u = tid + t * 256;
            int r = u >> 4, c4 = u & 15;
            *(float4*)&Hs[r][c4 * 4] = *(const float4*)&H[(size_t)(row0 + r) * 256 + kk + c4 * 4];
            *(float4*)&Ws[r][c4 * 4] = *(const float4*)&W[(size_t)(kk + r) * 64 + c4 * 4];
        }
        __syncthreads();
#pragma unroll 8
        for (int k = 0; k < 64; k++) {
            float4 w4 = *(const float4*)&Ws[k][tc * 4];
            unsigned long long w01, w23;
            asm("mov.b64 %0, {%1, %2};" : "=l"(w01) : "f"(w4.x), "f"(w4.y));
            asm("mov.b64 %0, {%1, %2};" : "=l"(w23) : "f"(w4.z), "f"(w4.w));
#pragma unroll
            for (int q = 0; q < 4; q++) {
                float h = Hs[tr * 4 + q][k];
                unsigned long long hp;
                asm("mov.b64 %0, {%1, %1};" : "=l"(hp) : "f"(h));
                asm("fma.rn.f32x2 %0, %1, %2, %0;" : "+l"(acc[q * 2 + 0]) : "l"(hp), "l"(w01));
                asm("fma.rn.f32x2 %0, %1, %2, %0;" : "+l"(acc[q * 2 + 1]) : "l"(hp), "l"(w23));
            }
        }
        __syncthreads();
    }

    float v[4][4];
#pragma unroll
    for (int q = 0; q < 4; q++) {
        v[q][0] = __uint_as_float((uint32_t)acc[q * 2 + 0]);
        v[q][1] = __uint_as_float((uint32_t)(acc[q * 2 + 0] >> 32));
        v[q][2] = __uint_as_float((uint32_t)acc[q * 2 + 1]);
        v[q][3] = __uint_as_float((uint32_t)(acc[q * 2 + 1] >> 32));
    }
    float a1c[4], a2c[4];
#pragma unroll
    for (int c = 0; c < 4; c++) {
        a1c[c] = __ldg(&a[tc * 4 + c]);
        a2c[c] = __ldg(&a[64 + tc * 4 + c]);
    }
#pragma unroll
    for (int q = 0; q < 4; q++) {
        int i = row0 + tr * 4 + q;
        *(float4*)&g_Wh[(size_t)i * 64 + tc * 4] = make_float4(v[q][0], v[q][1], v[q][2], v[q][3]);
        float p1 = v[q][0] * a1c[0] + v[q][1] * a1c[1] + v[q][2] * a1c[2] + v[q][3] * a1c[3];
        float p2 = v[q][0] * a2c[0] + v[q][1] * a2c[1] + v[q][2] * a2c[2] + v[q][3] * a2c[3];
#pragma unroll
        for (int off = 1; off < 16; off <<= 1) {
            p1 += __shfl_xor_sync(0xffffffffu, p1, off);
            p2 += __shfl_xor_sync(0xffffffffu, p2, off);
        }
        if (tc == 0) {
            g_e1[i] = p1;
            g_e2[i] = p2;
            g_E1[i] = __expf(p2);
            g_E2[i] = __expf(ALPHA * p2);
        }
    }
}

// ---------------- K2: per-row m, A, B, thE, 1/denominator (smem-staged) ------
__global__ __launch_bounds__(256) void k2_denom() {
    __shared__ float sE1[NV];
    __shared__ float sE2[NV];
    __shared__ float red[8];
    int tid = threadIdx.x;
#pragma unroll
    for (int t = 0; t < 4; t++) {
        ((float4*)sE1)[tid + t * 256] = ((const float4*)g_E1)[tid + t * 256];
        ((float4*)sE2)[tid + t * 256] = ((const float4*)g_E2)[tid + t * 256];
    }
    float mx = -1e30f;
#pragma unroll
    for (int t = 0; t < 4; t++) {
        float4 v = ((const float4*)g_e2)[tid + t * 256];
        mx = fmaxf(fmaxf(mx, v.x), fmaxf(fmaxf(v.y, v.z), v.w));
    }
#pragma unroll
    for (int o = 16; o > 0; o >>= 1) mx = fmaxf(mx, __shfl_xor_sync(0xffffffffu, mx, o));
    if ((tid & 31) == 0) red[tid >> 5] = mx;
    __syncthreads();
    float e2max = red[0];
#pragma unroll
    for (int w = 1; w < 8; w++) e2max = fmaxf(e2max, red[w]);

    int il = tid >> 4;
    int sub = tid & 15;
    int i = blockIdx.x * 16 + il;
    float e1v = g_e1[i];
    float s = e1v + e2max;
    float m = s > 0.f ? s : ALPHA * s;
    float A = __expf(e1v - m);
    float B = __expf(ALPHA * e1v - m);
    float thE = __expf(-e1v);

    float d = 0.f;
#pragma unroll 4
    for (int t = 0; t < 64; t++) {
        int j = sub * 4 + t * 64;
        float4 E1v = *(const float4*)&sE1[j];
        float4 E2v = *(const float4*)&sE2[j];
        d += (E1v.x > thE) ? A * E1v.x : B * E2v.x;
        d += (E1v.y > thE) ? A * E1v.y : B * E2v.y;
        d += (E1v.z > thE) ? A * E1v.z : B * E2v.z;
        d += (E1v.w > thE) ? A * E1v.w : B * E2v.w;
    }
#pragma unroll
    for (int o = 8; o > 0; o >>= 1) d += __shfl_xor_sync(0xffffffffu, d, o);
    if (sub == 0) {
        g_A[i] = A; g_B[i] = B; g_thE[i] = thE;
        g_dinv[i] = 1.f / d;
    }
}

// ---------------- K3: masked weighted GEMM, 8i x 4c register tiles -----------
// Grid: 32 row-blocks (128 i) x 8 j-segments (512 j) = 256 CTAs, 256 thr,
// 2 CTAs/SM (32K regs + 52KB smem each).
// Per 64-j chunk: build ws[j][128 i] (i-contiguous f32x2 pairs) + whs[j][64 c];
// inner loop per j: 3 LDS.128 + 4 dup-movs + 16 FFMA2.
#define K3_SMEM 53248
__global__ __launch_bounds__(256, 2) void k3_main(const int* __restrict__ adj) {
    extern __shared__ float sm[];
    float* ws  = sm;            // [64][128]
    float* whs = sm + 8192;     // [64][64]
    float* sE1 = sm + 12288;    // [512]
    float* sE2 = sm + 12800;    // [512]

    int tid = threadIdx.x;
    int br = blockIdx.x >> 3;          // 0..31
    int jseg = blockIdx.x & 7;         // 0..7
    int jbase = jseg << 9;             // *512

    if (tid < 128) {
        ((float4*)sE1)[tid] = ((const float4*)(g_E1 + jbase))[tid];
        ((float4*)sE2)[tid] = ((const float4*)(g_E2 + jbase))[tid];
    }

    // build role: row bi, j-half jh (32 j)
    int bi = tid & 127;
    int jh = (tid >> 7) * 32;
    int gi = br * 128 + bi;
    float Ai = __ldg(&g_A[gi]), Bi = __ldg(&g_B[gi]), th = __ldg(&g_thE[gi]);
    const int4* adjp = (const int4*)(adj + (size_t)gi * NV + jbase + jh);

    // compute role: rows tr*8..+7, cols tc*4..+3
    int tr = tid >> 4;
    int tc = tid & 15;

    unsigned long long acc[16];
#pragma unroll
    for (int q = 0; q < 16; q++) acc[q] = 0ull;

    int4 pref[8];
#pragma unroll
    for (int q = 0; q < 8; q++) pref[q] = __ldg(adjp + q);

    for (int ch = 0; ch < 8; ++ch) {
        __syncthreads();   // prev chunk consumed (covers E staging on ch=0)

        // load Wh chunk: 64 rows x 64 cols
#pragma unroll
        for (int t = 0; t < 4; t++) {
            int u = tid + t * 256;
            int r = u >> 4, c4 = u & 15;
            *(float4*)&whs[r * 64 + c4 * 4] =
                *(const float4*)&g_Wh[(size_t)(jbase + ch * 64 + r) * 64 + c4 * 4];
        }
        // build masked-weight tile ws[j][i] from pref
#pragma unroll
        for (int q = 0; q < 8; q++) {
            int4 av = pref[q];
            int jl = ch * 64 + jh + q * 4;
            float4 e1 = *(const float4*)&sE1[jl];
            float4 e2 = *(const float4*)&sE2[jl];
            float w0 = (av.x > 0) ? ((e1.x > th) ? Ai * e1.x : Bi * e2.x) : 0.f;
            float w1 = (av.y > 0) ? ((e1.y > th) ? Ai * e1.y : Bi * e2.y) : 0.f;
            float w2 = (av.z > 0) ? ((e1.z > th) ? Ai * e1.z : Bi * e2.z) : 0.f;
            float w3 = (av.w > 0) ? ((e1.w > th) ? Ai * e1.w : Bi * e2.w) : 0.f;
            int jr = (jh + q * 4) * 128 + bi;
            ws[jr]       = w0;
            ws[jr + 128] = w1;
            ws[jr + 256] = w2;
            ws[jr + 384] = w3;
        }
        if (ch < 7) {
#pragma unroll
            for (int q = 0; q < 8; q++) pref[q] = __ldg(adjp + (ch + 1) * 16 + q);
        }
        __syncthreads();

#pragma unroll 4
        for (int jj = 0; jj < 64; jj++) {
            ulonglong2 wA = *(const ulonglong2*)&ws[jj * 128 + tr * 8];
            ulonglong2 wB = *(const ulonglong2*)&ws[jj * 128 + tr * 8 + 4];
            float4 wh = *(const float4*)&whs[jj * 64 + tc * 4];
            unsigned long long d0, d1, d2, d3;
            asm("mov.b64 %0, {%1, %1};" : "=l"(d0) : "f"(wh.x));
            asm("mov.b64 %0, {%1, %1};" : "=l"(d1) : "f"(wh.y));
            asm("mov.b64 %0, {%1, %1};" : "=l"(d2) : "f"(wh.z));
            asm("mov.b64 %0, {%1, %1};" : "=l"(d3) : "f"(wh.w));
            asm("fma.rn.f32x2 %0, %1, %2, %0;" : "+l"(acc[0])  : "l"(wA.x), "l"(d0));
            asm("fma.rn.f32x2 %0, %1, %2, %0;" : "+l"(acc[1])  : "l"(wA.x), "l"(d1));
            asm("fma.rn.f32x2 %0, %1, %2, %0;" : "+l"(acc[2])  : "l"(wA.x), "l"(d2));
            asm("fma.rn.f32x2 %0, %1, %2, %0;" : "+l"(acc[3])  : "l"(wA.x), "l"(d3));
            asm("fma.rn.f32x2 %0, %1, %2, %0;" : "+l"(acc[4])  : "l"(wA.y), "l"(d0));
            asm("fma.rn.f32x2 %0, %1, %2, %0;" : "+l"(acc[5])  : "l"(wA.y), "l"(d1));
            asm("fma.rn.f32x2 %0, %1, %2, %0;" : "+l"(acc[6])  : "l"(wA.y), "l"(d2));
            asm("fma.rn.f32x2 %0, %1, %2, %0;" : "+l"(acc[7])  : "l"(wA.y), "l"(d3));
            asm("fma.rn.f32x2 %0, %1, %2, %0;" : "+l"(acc[8])  : "l"(wB.x), "l"(d0));
            asm("fma.rn.f32x2 %0, %1, %2, %0;" : "+l"(acc[9])  : "l"(wB.x), "l"(d1));
            asm("fma.rn.f32x2 %0, %1, %2, %0;" : "+l"(acc[10]) : "l"(wB.x), "l"(d2));
            asm("fma.rn.f32x2 %0, %1, %2, %0;" : "+l"(acc[11]) : "l"(wB.x), "l"(d3));
            asm("fma.rn.f32x2 %0, %1, %2, %0;" : "+l"(acc[12]) : "l"(wB.y), "l"(d0));
            asm("fma.rn.f32x2 %0, %1, %2, %0;" : "+l"(acc[13]) : "l"(wB.y), "l"(d1));
            asm("fma.rn.f32x2 %0, %1, %2, %0;" : "+l"(acc[14]) : "l"(wB.y), "l"(d2));
            asm("fma.rn.f32x2 %0, %1, %2, %0;" : "+l"(acc[15]) : "l"(wB.y), "l"(d3));
        }
    }

    // write partials
    float* base = &g_part[jseg][(size_t)(br * 128 + tr * 8) * 64 + tc * 4];
#pragma unroll
    for (int ip = 0; ip < 4; ip++) {
        float4 lo, hi;
        lo.x = __uint_as_float((uint32_t)acc[ip * 4 + 0]);
        lo.y = __uint_as_float((uint32_t)acc[ip * 4 + 1]);
        lo.z = __uint_as_float((uint32_t)acc[ip * 4 + 2]);
        lo.w = __uint_as_float((uint32_t)acc[ip * 4 + 3]);
        hi.x = __uint_as_float((uint32_t)(acc[ip * 4 + 0] >> 32));
        hi.y = __uint_as_float((uint32_t)(acc[ip * 4 + 1] >> 32));
        hi.z = __uint_as_float((uint32_t)(acc[ip * 4 + 2] >> 32));
        hi.w = __uint_as_float((uint32_t)(acc[ip * 4 + 3] >> 32));
        *(float4*)(base + (ip * 2) * 64)     = lo;
        *(float4*)(base + (ip * 2 + 1) * 64) = hi;
    }
}

// ---------------- K4: combine 8 partials, scale, ELU (vectorized) -----------
__global__ __launch_bounds__(256) void k4_out(float* __restrict__ out) {
    int v4 = blockIdx.x * 256 + threadIdx.x;
    float4 s = ((const float4*)g_part[0])[v4];
#pragma unroll
    for (int p = 1; p < 8; p++) {
        float4 t = ((const float4*)g_part[p])[v4];
        s.x += t.x; s.y += t.y; s.z += t.z; s.w += t.w;
    }
    int i = v4 >> 4;
    float di = g_dinv[i];
    s.x *= di; s.y *= di; s.z *= di; s.w *= di;
    s.x = s.x > 0.f ? s.x : (__expf(s.x) - 1.f);
    s.y = s.y > 0.f ? s.y : (__expf(s.y) - 1.f);
    s.z = s.z > 0.f ? s.z : (__expf(s.z) - 1.f);
    s.w = s.w > 0.f ? s.w : (__expf(s.w) - 1.f);
    ((float4*)out)[v4] = s;
}

// ---------------- launch ----------------
extern "C" void kernel_launch(void* const* d_in, const int* in_sizes, int n_in,
                              void* d_out, int out_size) {
    const float* H = (const float*)d_in[0];
    const int* adj = (const int*)d_in[1];
    const float* W = (const float*)d_in[2];
    const float* a = (const float*)d_in[3];
    float* out = (float*)d_out;

    cudaFuncSetAttribute(k3_main, cudaFuncAttributeMaxDynamicSharedMemorySize, K3_SMEM);

    k1_wh<<<64, 256>>>(H, W, a);
    k2_denom<<<256, 256>>>();
    k3_main<<<256, 256, K3_SMEM>>>(adj);
    k4_out<<<256, 256>>>(out);
}